// round 7
// baseline (speedup 1.0000x reference)
#include <cuda_runtime.h>
#include <math.h>

// ---------------- scratch (static device allocations) ----------------
__device__ float g_band[8 * 1024 * 65];   // banded ATA -> L, [b][col][d], fp32
__device__ float g_atb[8 * 1024];         // rhs
__device__ float g_t[2 * 2 * 64 * 1024];  // conv1 outputs [branch][n][c][px]
__device__ float g_att[2 * 24 * 1024];    // sigmoid(conv2 att)
__device__ float g_grad[2 * 24 * 1024];   // conv2 grad
__device__ float g_se[2 * 4];
__device__ float g_sol[8 * 1024];
__device__ float g_ygn[2 * 4 * 1024];

// ---------------- conv1: 64->64 3x3, lrelu, both branches ----------------
__global__ void __launch_bounds__(256) k_conv1(
    const float* __restrict__ x,
    const float* __restrict__ gw1, const float* __restrict__ gb1,
    const float* __restrict__ aw1, const float* __restrict__ ab1)
{
    int plane  = blockIdx.x;           // 0..255
    int branch = plane >> 7;           // 0=grad, 1=att
    int n      = (plane >> 6) & 1;
    int co     = plane & 63;
    const float* wgt  = (branch ? aw1 : gw1) + co * 576;
    float bias        = (branch ? ab1 : gb1)[co];

    __shared__ float xs[34 * 34];
    int row  = threadIdx.x >> 3;        // 0..31
    int col0 = (threadIdx.x & 7) << 2;  // 0..28 step 4

    float a0 = bias, a1 = bias, a2 = bias, a3 = bias;
    const float* xbase = x + n * 64 * 1024;

    for (int ci = 0; ci < 64; ci++) {
        __syncthreads();
        const float* xp = xbase + ci * 1024;
        for (int idx = threadIdx.x; idx < 1156; idx += 256) {
            int r = idx / 34, c = idx - r * 34;
            int gr = r - 1, gc = c - 1;
            xs[idx] = ((unsigned)gr < 32u && (unsigned)gc < 32u) ? xp[gr * 32 + gc] : 0.f;
        }
        __syncthreads();
        float w[9];
#pragma unroll
        for (int k = 0; k < 9; k++) w[k] = __ldg(wgt + ci * 9 + k);
        float s[3][6];
#pragma unroll
        for (int dy = 0; dy < 3; dy++)
#pragma unroll
            for (int dx = 0; dx < 6; dx++)
                s[dy][dx] = xs[(row + dy) * 34 + col0 + dx];
#pragma unroll
        for (int dy = 0; dy < 3; dy++) {
            float w0 = w[dy * 3], w1 = w[dy * 3 + 1], w2 = w[dy * 3 + 2];
            a0 += w0 * s[dy][0] + w1 * s[dy][1] + w2 * s[dy][2];
            a1 += w0 * s[dy][1] + w1 * s[dy][2] + w2 * s[dy][3];
            a2 += w0 * s[dy][2] + w1 * s[dy][3] + w2 * s[dy][4];
            a3 += w0 * s[dy][3] + w1 * s[dy][4] + w2 * s[dy][5];
        }
    }
    float* out = g_t + (((branch * 2 + n) * 64 + co) * 1024) + row * 32 + col0;
    out[0] = a0 > 0.f ? a0 : 0.01f * a0;
    out[1] = a1 > 0.f ? a1 : 0.01f * a1;
    out[2] = a2 > 0.f ? a2 : 0.01f * a2;
    out[3] = a3 > 0.f ? a3 : 0.01f * a3;
}

// ---------------- conv2: 64->24 3x3 (+sigmoid on att branch) ----------------
__global__ void __launch_bounds__(256) k_conv2(
    const float* __restrict__ gw2, const float* __restrict__ gb2,
    const float* __restrict__ aw2, const float* __restrict__ ab2)
{
    int plane  = blockIdx.x;            // 0..95
    int branch = plane / 48;
    int rem    = plane - branch * 48;
    int n      = rem / 24;
    int co     = rem - n * 24;
    const float* wgt = (branch ? aw2 : gw2) + co * 576;
    float bias       = (branch ? ab2 : gb2)[co];

    __shared__ float xs[34 * 34];
    int row  = threadIdx.x >> 3;
    int col0 = (threadIdx.x & 7) << 2;

    float a0 = bias, a1 = bias, a2 = bias, a3 = bias;
    const float* xbase = g_t + (branch * 2 + n) * 64 * 1024;

    for (int ci = 0; ci < 64; ci++) {
        __syncthreads();
        const float* xp = xbase + ci * 1024;
        for (int idx = threadIdx.x; idx < 1156; idx += 256) {
            int r = idx / 34, c = idx - r * 34;
            int gr = r - 1, gc = c - 1;
            xs[idx] = ((unsigned)gr < 32u && (unsigned)gc < 32u) ? xp[gr * 32 + gc] : 0.f;
        }
        __syncthreads();
        float w[9];
#pragma unroll
        for (int k = 0; k < 9; k++) w[k] = __ldg(wgt + ci * 9 + k);
        float s[3][6];
#pragma unroll
        for (int dy = 0; dy < 3; dy++)
#pragma unroll
            for (int dx = 0; dx < 6; dx++)
                s[dy][dx] = xs[(row + dy) * 34 + col0 + dx];
#pragma unroll
        for (int dy = 0; dy < 3; dy++) {
            float w0 = w[dy * 3], w1 = w[dy * 3 + 1], w2 = w[dy * 3 + 2];
            a0 += w0 * s[dy][0] + w1 * s[dy][1] + w2 * s[dy][2];
            a1 += w0 * s[dy][1] + w1 * s[dy][2] + w2 * s[dy][3];
            a2 += w0 * s[dy][2] + w1 * s[dy][3] + w2 * s[dy][4];
            a3 += w0 * s[dy][3] + w1 * s[dy][4] + w2 * s[dy][5];
        }
    }
    float* out = (branch ? g_att : g_grad) + ((n * 24 + co) * 1024) + row * 32 + col0;
    if (branch) {
        out[0] = 1.f / (1.f + expf(-a0));
        out[1] = 1.f / (1.f + expf(-a1));
        out[2] = 1.f / (1.f + expf(-a2));
        out[3] = 1.f / (1.f + expf(-a3));
    } else {
        out[0] = a0; out[1] = a1; out[2] = a2; out[3] = a3;
    }
}

// ---------------- SE branch ----------------
__global__ void __launch_bounds__(256) k_se(
    const float* __restrict__ x,
    const float* __restrict__ sw1, const float* __restrict__ sb1,
    const float* __restrict__ sw2, const float* __restrict__ sb2)
{
    int n = blockIdx.x, tid = threadIdx.x;
    __shared__ float red[256];
    __shared__ float pooled[64];
    __shared__ float s1[32];

    int c = tid >> 2, part = tid & 3;
    const float* xp = x + (n * 64 + c) * 1024 + part * 256;
    float s = 0.f;
    for (int i = 0; i < 256; i++) s += xp[i];
    red[tid] = s;
    __syncthreads();
    if (part == 0)
        pooled[c] = (red[tid] + red[tid + 1] + red[tid + 2] + red[tid + 3]) * (1.f / 1024.f);
    __syncthreads();
    if (tid < 32) {
        float a = sb1[tid];
        for (int j = 0; j < 64; j++) a += sw1[tid * 64 + j] * pooled[j];
        s1[tid] = a > 0.f ? a : 0.01f * a;
    }
    __syncthreads();
    if (tid < 4) {
        float a = sb2[tid];
        for (int j = 0; j < 32; j++) a += sw2[tid * 32 + j] * s1[j];
        g_se[n * 4 + tid] = 1.f / (1.f + expf(-a));
    }
}

// ---------------- build banded ATA + ATB: deterministic gather ----------------
__global__ void __launch_bounds__(256) k_build(const float* __restrict__ a)
{
    int t = blockIdx.x * blockDim.x + threadIdx.x;   // 0..8191
    int b = t >> 10;
    int q = t & 1023;
    int n = b >> 2;
    int g = b & 3;
    const int offs[7] = {0, 1, 2, 31, 32, 33, 64};

    float acc[11];
    const int DVALS[11] = {0, 1, 2, 29, 30, 31, 32, 33, 62, 63, 64};
#pragma unroll
    for (int z = 0; z < 11; z++) acc[z] = 0.f;
    acc[0] = 1e-12f;
    float atb = 0.f;

#pragma unroll
    for (int k = 0; k < 6; k++) {
        int ch = g * 6 + k;
        const float* attp  = g_att  + (n * 24 + ch) * 1024;
        const float* gradp = g_grad + (n * 24 + ch) * 1024;
#pragma unroll
        for (int c2 = 0; c2 < 7; c2++) {
            int i = q - offs[c2];
            if (i >= 0) {
                float attv = attp[i];
                float at2  = attv * attv;
                const float* arow = a + (size_t)(i * 6 + k) * 1024;
                float v2 = arow[q];
                if (v2 != 0.f) {
                    atb += v2 * at2 * gradp[i];
                    float w2 = v2 * at2;
#pragma unroll
                    for (int c1 = c2; c1 < 7; c1++) {
                        int col1 = i + offs[c1];
                        if (col1 <= 1023) {
                            float contrib = arow[col1] * w2;
                            int d = offs[c1] - offs[c2];
#pragma unroll
                            for (int z = 0; z < 11; z++)
                                if (DVALS[z] == d) acc[z] += contrib;
                        }
                    }
                }
            }
        }
    }

    float* bc = g_band + ((size_t)b * 1024 + q) * 65;
#pragma unroll
    for (int d = 0; d < 65; d++) {
        float v = 0.f;
#pragma unroll
        for (int z = 0; z < 11; z++)
            if (DVALS[z] == d) v = acc[z];
        bc[d] = v;
    }
    g_atb[b * 1024 + q] = atb;
}

// ---------------- banded Cholesky, fp32, 512 thr, conflict-free chunks -------
// W ring: 65 columns x 65 diag entries, slot = col % 65, stride 65 (odd ->
// stride-1 lane access conflict-free). Cells (p=1..63, d): row-chunks of 32
// consecutive d per warp (lane = d offset): 95 real chunks + 3 dummy chunks
// (scratch at W[4225..]) = 98 = 14 worker warps x 7 chunks. lq = Lb[p+d0+lane]
// stride-1; zero pad Lsm[65..95] makes out-of-band updates exact no-ops.
// Warps 14,15 = committer (diag, L writeout, fwd-sub, commit col j+64,
// 4-deep LDG prefetch FIFO); lane 0 doubles for r=64, lane 1 publishes the
// d=64 entry of col j+1. Chunks (p=1) publish col j+1; warp0 lane0 computes
// next pivot rsqrt. One __syncthreads per column.
__global__ void __launch_bounds__(512) k_solve()
{
    int b    = blockIdx.x;
    int tid  = threadIdx.x;
    int wid  = tid >> 5;
    int lane = tid & 31;
    float* band = g_band + (size_t)b * 1024 * 65;

    __shared__ float W[4420];        // 65*65 ring + 3*65 dummy scratch
    __shared__ float Lsm[192];       // 2 x 96; d=65..95 pad = 0
    __shared__ float y_s[1100];
    __shared__ float x_s[1024];
    __shared__ float s_inv[2];

    // ---------- worker chunk decode (warps 0..13), all static indices ------
    int pp[7], qb[7], A[7], pi0[7];
    bool dum[7], pub[7], sfl[7];
#pragma unroll
    for (int i = 0; i < 7; i++) {
        int c = wid + 14 * i;            // 0..97
        bool dm = (c >= 95);
        int p, d0;
        if (c < 64)       { p = (c >> 1) + 1; d0 = (c & 1) << 5; }
        else if (!dm)     { p = c - 31;       d0 = 0; }
        else              { p = 2;            d0 = 0; }
        pp[i]  = p;
        qb[i]  = dm ? 95 : (p + d0 + lane);
        A[i]   = dm ? (4225 + (c - 95) * 65 + lane) : (p * 65 + d0 + lane);
        dum[i] = dm;
        pub[i] = (c <= 1);               // chunks (p=1,d0=0) and (p=1,d0=32)
        pi0[i] = d0 + lane;
        sfl[i] = (c == 0) && (lane == 0);
    }

    // ---------- committer state (warps 14,15; k = 0..63) ----------
    int k  = tid - 448;
    int lw = k;                          // band L-writeout index (j*65 + k)
    int cm = 4160 + k;                   // W commit addr (col 64 slot)
    int pf = 4420 + k;                   // gmem prefetch index (col 68)
    float P0 = 0.f, P1 = 0.f, P2 = 0.f, P3 = 0.f;   // FIFO r=k
    float Q0 = 0.f, Q1 = 0.f, Q2 = 0.f, Q3 = 0.f;   // FIFO r=64 (lane k==0)
    int a65 = 129;                       // k==1: W addr of (col j+1, d=64)

    // ---------- init ----------
    for (int j = tid; j < 1024; j += 512) y_s[j] = g_atb[b * 1024 + j];
    for (int j = 1024 + tid; j < 1100; j += 512) y_s[j] = 0.f;
    for (int idx = tid; idx < 4160; idx += 512) W[idx] = band[idx];
    if (tid < 31)       Lsm[65 + tid] = 0.f;
    else if (tid < 62)  Lsm[96 + 65 + (tid - 31)] = 0.f;
    if (wid >= 14) {
        P0 = band[4160 + k];
        P1 = band[4225 + k];
        P2 = band[4290 + k];
        P3 = band[4355 + k];
        if (k == 0) {
            Q0 = band[4224]; Q1 = band[4289];
            Q2 = band[4354]; Q3 = band[4419];
        }
    }
    __syncthreads();
    if (tid < 65) {
        Lsm[tid] = W[tid];               // publish column 0
        if (tid == 0) {
            float d0 = W[0];
            float rr = rsqrtf(d0);
            s_inv[0] = rr * (1.5f - 0.5f * d0 * rr * rr);
        }
    }
    __syncthreads();

    // ---------- main factorization loop: 1 barrier per column ----------
    for (int j = 0; j < 1024; j++) {
        int bb = j & 1;
        int nb = bb ^ 1;
        const float* Lb = Lsm + bb * 96;
        float inv  = s_inv[bb];
        float inv2 = inv * inv;
        bool have_in = (j < 960);
        int nb96 = nb * 96;

        if (wid < 14) {
            // software pipeline: load chunk i+1 before storing chunk i
            float lp = Lb[pp[0]];
            float lq = Lb[qb[0]];
            float wv = W[A[0]];
#pragma unroll
            for (int i = 0; i < 7; i++) {
                float lpn = 0.f, lqn = 0.f, wvn = 0.f;
                if (i < 6) {
                    lpn = Lb[pp[i + 1]];
                    lqn = Lb[qb[i + 1]];
                    wvn = W[A[i + 1]];
                }
                float w2 = wv - lp * lq * inv2;
                W[A[i]] = w2;
                if (pub[i]) {
                    Lsm[nb96 + pi0[i]] = w2;     // publish col j+1
                    if (sfl[i]) {
                        float rr = rsqrtf(w2);
                        s_inv[nb] = rr * (1.5f - 0.5f * w2 * rr * rr);
                    }
                }
                if (!dum[i]) {
                    A[i] += 65; if (A[i] >= 4225) A[i] -= 4225;
                }
                lp = lpn; lq = lqn; wv = wvn;
            }
        } else {
            float yj = y_s[j];
            float yji = yj * inv;
            if (k == 0) {
                band[lw] = inv;                  // store INVERSE diag
                x_s[j] = yji;
                float l64 = Lb[64];
                if (have_in) W[cm] = P0 - l64 * l64 * inv2;  // + pair (64,64)
                // r = 64 duties
                float L64 = l64 * inv;
                band[lw + 64] = L64;
                y_s[j + 64] -= L64 * yji;
                if (have_in) W[cm + 64] = Q0;
                Q0 = Q1; Q1 = Q2; Q2 = Q3;
                Q3 = (pf + 64 < 66560) ? band[pf + 64] : 0.f;
            } else {
                float wv = Lb[k];
                float Lr = wv * inv;
                band[lw] = Lr;                   // L write-out
                y_s[j + k] -= Lr * yji;          // forward-sub
                if (have_in) W[cm] = P0;         // commit col j+64
                if (k == 1) {                    // publish (col j+1, d=64)
                    Lsm[nb96 + 64] = W[a65];
                    a65 += 65; if (a65 >= 4225) a65 -= 4225;
                }
            }
            P0 = P1; P1 = P2; P2 = P3;
            P3 = (pf < 66560) ? band[pf] : 0.f;
            pf += 65;
            cm += 65; if (cm >= 4225) cm -= 4225;
            lw += 65;
        }
        __syncthreads();
    }

    // ---------- back substitution: L^T x = y', blocked by 64 rows ----------
    float* LB = W;
    for (int blk = 15; blk >= 0; blk--) {
        int j0 = blk * 64;
        for (int idx = tid; idx < 64 * 65; idx += 512)
            LB[idx] = band[j0 * 65 + idx];
        __syncthreads();
        if (tid < 64) {
            int t = tid, jj = j0 + t;
            float s = 0.f;
            for (int rr = 64 - t; rr <= 64; rr++) {
                int jr = jj + rr;
                if (jr < 1024) s += LB[t * 65 + rr] * x_s[jr];
            }
            x_s[jj] -= s;
        }
        __syncthreads();
        for (int t = 63; t >= 1; t--) {
            float xval = x_s[j0 + t] * LB[t * 65];
            if (tid < t) x_s[j0 + tid] -= LB[tid * 65 + (t - tid)] * xval;
            __syncthreads();
        }
        if (tid < 64) x_s[j0 + tid] *= LB[tid * 65];
        __syncthreads();
    }

    for (int j = tid; j < 1024; j += 512) g_sol[b * 1024 + j] = x_s[j];
}

// ---------------- GroupNorm(1, GR) + affine + SE scale ----------------
__global__ void __launch_bounds__(256) k_gn(const float* __restrict__ gn_g,
                                            const float* __restrict__ gn_b)
{
    int n = blockIdx.x, tid = threadIdx.x;
    __shared__ double s1[256], s2[256];
    double a = 0.0, c = 0.0;
    for (int idx = tid; idx < 4096; idx += 256) {
        double v = g_sol[n * 4096 + idx];
        a += v; c += v * v;
    }
    s1[tid] = a; s2[tid] = c;
    __syncthreads();
    for (int off = 128; off > 0; off >>= 1) {
        if (tid < off) { s1[tid] += s1[tid + off]; s2[tid] += s2[tid + off]; }
        __syncthreads();
    }
    double mu  = s1[0] * (1.0 / 4096.0);
    double var = s2[0] * (1.0 / 4096.0) - mu * mu;
    double invstd = rsqrt(var + 1e-5);
    for (int idx = tid; idx < 4096; idx += 256) {
        int g = idx >> 10;
        float v = (float)((g_sol[n * 4096 + idx] - mu) * invstd);
        v = v * gn_g[g] + gn_b[g];
        v *= g_se[n * 4 + g];
        g_ygn[n * 4096 + idx] = v;
    }
}

// ---------------- final conv: 4->128 3x3 ----------------
__global__ void __launch_bounds__(256) k_convf(
    const float* __restrict__ pw, const float* __restrict__ pb,
    float* __restrict__ out)
{
    int plane = blockIdx.x;          // 0..255
    int n  = plane >> 7;
    int co = plane & 127;
    __shared__ float ys[4 * 1156];
    for (int idx = threadIdx.x; idx < 4 * 1156; idx += 256) {
        int ci = idx / 1156, rr = idx - ci * 1156;
        int r = rr / 34, c = rr - r * 34;
        int gr = r - 1, gc = c - 1;
        ys[idx] = ((unsigned)gr < 32u && (unsigned)gc < 32u)
                  ? g_ygn[(n * 4 + ci) * 1024 + gr * 32 + gc] : 0.f;
    }
    __syncthreads();

    const float* wgt = pw + co * 36;
    float bias = pb[co];
    int row  = threadIdx.x >> 3;
    int col0 = (threadIdx.x & 7) << 2;
    float a0 = bias, a1 = bias, a2 = bias, a3 = bias;
#pragma unroll
    for (int ci = 0; ci < 4; ci++) {
        float w[9];
#pragma unroll
        for (int k = 0; k < 9; k++) w[k] = __ldg(wgt + ci * 9 + k);
        float s[3][6];
#pragma unroll
        for (int dy = 0; dy < 3; dy++)
#pragma unroll
            for (int dx = 0; dx < 6; dx++)
                s[dy][dx] = ys[ci * 1156 + (row + dy) * 34 + col0 + dx];
#pragma unroll
        for (int dy = 0; dy < 3; dy++) {
            float w0 = w[dy * 3], w1 = w[dy * 3 + 1], w2 = w[dy * 3 + 2];
            a0 += w0 * s[dy][0] + w1 * s[dy][1] + w2 * s[dy][2];
            a1 += w0 * s[dy][1] + w1 * s[dy][2] + w2 * s[dy][3];
            a2 += w0 * s[dy][2] + w1 * s[dy][3] + w2 * s[dy][4];
            a3 += w0 * s[dy][3] + w1 * s[dy][4] + w2 * s[dy][5];
        }
    }
    float* o = out + ((n * 128 + co) * 1024) + row * 32 + col0;
    o[0] = a0; o[1] = a1; o[2] = a2; o[3] = a3;
}

// ---------------- launcher (reordered: k_solve is the 4th launch) ----------
extern "C" void kernel_launch(void* const* d_in, const int* in_sizes, int n_in,
                              void* d_out, int out_size)
{
    const float* x    = (const float*)d_in[0];
    const float* a    = (const float*)d_in[1];
    const float* gw1  = (const float*)d_in[2];
    const float* gb1  = (const float*)d_in[3];
    const float* gw2  = (const float*)d_in[4];
    const float* gb2  = (const float*)d_in[5];
    const float* aw1  = (const float*)d_in[6];
    const float* ab1  = (const float*)d_in[7];
    const float* aw2  = (const float*)d_in[8];
    const float* ab2  = (const float*)d_in[9];
    const float* sw1  = (const float*)d_in[10];
    const float* sb1  = (const float*)d_in[11];
    const float* sw2  = (const float*)d_in[12];
    const float* sb2  = (const float*)d_in[13];
    const float* gn_g = (const float*)d_in[14];
    const float* gn_b = (const float*)d_in[15];
    const float* pw   = (const float*)d_in[16];
    const float* pb   = (const float*)d_in[17];
    float* out = (float*)d_out;

    k_conv1<<<256, 256>>>(x, gw1, gb1, aw1, ab1);
    k_conv2<<<96, 256>>>(gw2, gb2, aw2, ab2);
    k_build<<<32, 256>>>(a);
    k_solve<<<8, 512>>>();
    k_se<<<2, 256>>>(x, sw1, sb1, sw2, sb2);
    k_gn<<<2, 256>>>(gn_g, gn_b);
    k_convf<<<256, 256>>>(pw, pb, out);
}

// round 8
// speedup vs baseline: 1.3227x; 1.3227x over previous
#include <cuda_runtime.h>
#include <math.h>

// ---------------- scratch (static device allocations) ----------------
__device__ float g_band[8 * 1024 * 65];   // banded ATA -> L, [b][col][d], fp32
__device__ float g_atb[8 * 1024];         // rhs
__device__ float g_t[2 * 2 * 64 * 1024];  // conv1 outputs [branch][n][c][px]
__device__ float g_att[2 * 24 * 1024];    // sigmoid(conv2 att)
__device__ float g_grad[2 * 24 * 1024];   // conv2 grad
__device__ float g_se[2 * 4];
__device__ float g_sol[8 * 1024];
__device__ float g_ygn[2 * 4 * 1024];

// ---------------- conv1: 64->64 3x3, lrelu, both branches ----------------
__global__ void __launch_bounds__(256) k_conv1(
    const float* __restrict__ x,
    const float* __restrict__ gw1, const float* __restrict__ gb1,
    const float* __restrict__ aw1, const float* __restrict__ ab1)
{
    int plane  = blockIdx.x;           // 0..255
    int branch = plane >> 7;           // 0=grad, 1=att
    int n      = (plane >> 6) & 1;
    int co     = plane & 63;
    const float* wgt  = (branch ? aw1 : gw1) + co * 576;
    float bias        = (branch ? ab1 : gb1)[co];

    __shared__ float xs[34 * 34];
    int row  = threadIdx.x >> 3;        // 0..31
    int col0 = (threadIdx.x & 7) << 2;  // 0..28 step 4

    float a0 = bias, a1 = bias, a2 = bias, a3 = bias;
    const float* xbase = x + n * 64 * 1024;

    for (int ci = 0; ci < 64; ci++) {
        __syncthreads();
        const float* xp = xbase + ci * 1024;
        for (int idx = threadIdx.x; idx < 1156; idx += 256) {
            int r = idx / 34, c = idx - r * 34;
            int gr = r - 1, gc = c - 1;
            xs[idx] = ((unsigned)gr < 32u && (unsigned)gc < 32u) ? xp[gr * 32 + gc] : 0.f;
        }
        __syncthreads();
        float w[9];
#pragma unroll
        for (int k = 0; k < 9; k++) w[k] = __ldg(wgt + ci * 9 + k);
        float s[3][6];
#pragma unroll
        for (int dy = 0; dy < 3; dy++)
#pragma unroll
            for (int dx = 0; dx < 6; dx++)
                s[dy][dx] = xs[(row + dy) * 34 + col0 + dx];
#pragma unroll
        for (int dy = 0; dy < 3; dy++) {
            float w0 = w[dy * 3], w1 = w[dy * 3 + 1], w2 = w[dy * 3 + 2];
            a0 += w0 * s[dy][0] + w1 * s[dy][1] + w2 * s[dy][2];
            a1 += w0 * s[dy][1] + w1 * s[dy][2] + w2 * s[dy][3];
            a2 += w0 * s[dy][2] + w1 * s[dy][3] + w2 * s[dy][4];
            a3 += w0 * s[dy][3] + w1 * s[dy][4] + w2 * s[dy][5];
        }
    }
    float* out = g_t + (((branch * 2 + n) * 64 + co) * 1024) + row * 32 + col0;
    out[0] = a0 > 0.f ? a0 : 0.01f * a0;
    out[1] = a1 > 0.f ? a1 : 0.01f * a1;
    out[2] = a2 > 0.f ? a2 : 0.01f * a2;
    out[3] = a3 > 0.f ? a3 : 0.01f * a3;
}

// ---------------- conv2: 64->24 3x3 (+sigmoid on att branch) ----------------
__global__ void __launch_bounds__(256) k_conv2(
    const float* __restrict__ gw2, const float* __restrict__ gb2,
    const float* __restrict__ aw2, const float* __restrict__ ab2)
{
    int plane  = blockIdx.x;            // 0..95
    int branch = plane / 48;
    int rem    = plane - branch * 48;
    int n      = rem / 24;
    int co     = rem - n * 24;
    const float* wgt = (branch ? aw2 : gw2) + co * 576;
    float bias       = (branch ? ab2 : gb2)[co];

    __shared__ float xs[34 * 34];
    int row  = threadIdx.x >> 3;
    int col0 = (threadIdx.x & 7) << 2;

    float a0 = bias, a1 = bias, a2 = bias, a3 = bias;
    const float* xbase = g_t + (branch * 2 + n) * 64 * 1024;

    for (int ci = 0; ci < 64; ci++) {
        __syncthreads();
        const float* xp = xbase + ci * 1024;
        for (int idx = threadIdx.x; idx < 1156; idx += 256) {
            int r = idx / 34, c = idx - r * 34;
            int gr = r - 1, gc = c - 1;
            xs[idx] = ((unsigned)gr < 32u && (unsigned)gc < 32u) ? xp[gr * 32 + gc] : 0.f;
        }
        __syncthreads();
        float w[9];
#pragma unroll
        for (int k = 0; k < 9; k++) w[k] = __ldg(wgt + ci * 9 + k);
        float s[3][6];
#pragma unroll
        for (int dy = 0; dy < 3; dy++)
#pragma unroll
            for (int dx = 0; dx < 6; dx++)
                s[dy][dx] = xs[(row + dy) * 34 + col0 + dx];
#pragma unroll
        for (int dy = 0; dy < 3; dy++) {
            float w0 = w[dy * 3], w1 = w[dy * 3 + 1], w2 = w[dy * 3 + 2];
            a0 += w0 * s[dy][0] + w1 * s[dy][1] + w2 * s[dy][2];
            a1 += w0 * s[dy][1] + w1 * s[dy][2] + w2 * s[dy][3];
            a2 += w0 * s[dy][2] + w1 * s[dy][3] + w2 * s[dy][4];
            a3 += w0 * s[dy][3] + w1 * s[dy][4] + w2 * s[dy][5];
        }
    }
    float* out = (branch ? g_att : g_grad) + ((n * 24 + co) * 1024) + row * 32 + col0;
    if (branch) {
        out[0] = 1.f / (1.f + expf(-a0));
        out[1] = 1.f / (1.f + expf(-a1));
        out[2] = 1.f / (1.f + expf(-a2));
        out[3] = 1.f / (1.f + expf(-a3));
    } else {
        out[0] = a0; out[1] = a1; out[2] = a2; out[3] = a3;
    }
}

// ---------------- SE branch ----------------
__global__ void __launch_bounds__(256) k_se(
    const float* __restrict__ x,
    const float* __restrict__ sw1, const float* __restrict__ sb1,
    const float* __restrict__ sw2, const float* __restrict__ sb2)
{
    int n = blockIdx.x, tid = threadIdx.x;
    __shared__ float red[256];
    __shared__ float pooled[64];
    __shared__ float s1[32];

    int c = tid >> 2, part = tid & 3;
    const float* xp = x + (n * 64 + c) * 1024 + part * 256;
    float s = 0.f;
    for (int i = 0; i < 256; i++) s += xp[i];
    red[tid] = s;
    __syncthreads();
    if (part == 0)
        pooled[c] = (red[tid] + red[tid + 1] + red[tid + 2] + red[tid + 3]) * (1.f / 1024.f);
    __syncthreads();
    if (tid < 32) {
        float a = sb1[tid];
        for (int j = 0; j < 64; j++) a += sw1[tid * 64 + j] * pooled[j];
        s1[tid] = a > 0.f ? a : 0.01f * a;
    }
    __syncthreads();
    if (tid < 4) {
        float a = sb2[tid];
        for (int j = 0; j < 32; j++) a += sw2[tid * 32 + j] * s1[j];
        g_se[n * 4 + tid] = 1.f / (1.f + expf(-a));
    }
}

// ---------------- build banded ATA + ATB: deterministic gather ----------------
__global__ void __launch_bounds__(256) k_build(const float* __restrict__ a)
{
    int t = blockIdx.x * blockDim.x + threadIdx.x;   // 0..8191
    int b = t >> 10;
    int q = t & 1023;
    int n = b >> 2;
    int g = b & 3;
    const int offs[7] = {0, 1, 2, 31, 32, 33, 64};

    float acc[11];
    const int DVALS[11] = {0, 1, 2, 29, 30, 31, 32, 33, 62, 63, 64};
#pragma unroll
    for (int z = 0; z < 11; z++) acc[z] = 0.f;
    acc[0] = 1e-12f;
    float atb = 0.f;

#pragma unroll
    for (int k = 0; k < 6; k++) {
        int ch = g * 6 + k;
        const float* attp  = g_att  + (n * 24 + ch) * 1024;
        const float* gradp = g_grad + (n * 24 + ch) * 1024;
#pragma unroll
        for (int c2 = 0; c2 < 7; c2++) {
            int i = q - offs[c2];
            if (i >= 0) {
                float attv = attp[i];
                float at2  = attv * attv;
                const float* arow = a + (size_t)(i * 6 + k) * 1024;
                float v2 = arow[q];
                if (v2 != 0.f) {
                    atb += v2 * at2 * gradp[i];
                    float w2 = v2 * at2;
#pragma unroll
                    for (int c1 = c2; c1 < 7; c1++) {
                        int col1 = i + offs[c1];
                        if (col1 <= 1023) {
                            float contrib = arow[col1] * w2;
                            int d = offs[c1] - offs[c2];
#pragma unroll
                            for (int z = 0; z < 11; z++)
                                if (DVALS[z] == d) acc[z] += contrib;
                        }
                    }
                }
            }
        }
    }

    float* bc = g_band + ((size_t)b * 1024 + q) * 65;
#pragma unroll
    for (int d = 0; d < 65; d++) {
        float v = 0.f;
#pragma unroll
        for (int z = 0; z < 11; z++)
            if (DVALS[z] == d) v = acc[z];
        bc[d] = v;
    }
    g_atb[b * 1024 + q] = atb;
}

// ---------------- banded Cholesky, fp32, rank-4 blocked (4 cols/step) --------
// Ring W: 72 slots x stride 68 (d = 0..64). slot(c) = c % 72. At step base j
// (j += 4), window holds cols j..j+67; incoming cols j+68..j+71 commit into
// slots of dead cols j-4..j-1 (72-deep ring -> no collision; cols >= 65 apart
// from the panel need no updates from it).
// Phase A (warp 16): finalize panel cols j..j+3 serially (each gets t'<t
// corrections), write scaled L into PNL[4][132] (zero-padded 65..131; entry 0
// holds the INVERSE diag), compute x pivots.
// Phase B (warps 0..15): 128 chunks (o in 4..67, d0 in {0,32}, lane = d):
// 4 fused FMAs per cell from PNL (out-of-band terms hit the zero pad).
// tid<260 also: L writeout (STG), commit prefetched col (STS), prefetch next
// (LDG); tid 260..323: forward-sub y updates for r = 4..67 (r=1..3 in phase A).
// Two __syncthreads per 4 columns.
__global__ void __launch_bounds__(544) k_solve()
{
    const int WS = 68, WTOT = 72 * WS;         // 4896
    int b    = blockIdx.x;
    int tid  = threadIdx.x;
    int wid  = tid >> 5;
    int lane = tid & 31;
    float* band = g_band + (size_t)b * 1024 * 65;

    __shared__ float W[4896];
    __shared__ float PNL[4 * 132];
    __shared__ float y_s[1100];
    __shared__ float x_s[1024];

    // ---- worker chunks: 8 scalar-register chunks per warp (wid 0..15) ----
#define CH_DECL(n) int A##n, OB##n, LP##n
#define CH_INIT(n, i) { int _idx = wid * 8 + (i); int _o = 4 + (_idx >> 1); \
        int _d0 = (_idx & 1) << 5; \
        A##n = _o * WS + _d0 + lane; OB##n = _o + _d0 + lane; LP##n = _o; }
#define CH_DO(n) { float _w = W[A##n]; \
        float _lp0 = PNL[LP##n],       _lq0 = PNL[OB##n]; \
        float _lp1 = PNL[LP##n + 131], _lq1 = PNL[OB##n + 131]; \
        float _lp2 = PNL[LP##n + 262], _lq2 = PNL[OB##n + 262]; \
        float _lp3 = PNL[LP##n + 393], _lq3 = PNL[OB##n + 393]; \
        _w -= _lp0 * _lq0; _w -= _lp1 * _lq1; \
        _w -= _lp2 * _lq2; _w -= _lp3 * _lq3; \
        W[A##n] = _w; A##n += 4 * WS; if (A##n >= WTOT) A##n -= WTOT; }

    CH_DECL(0); CH_DECL(1); CH_DECL(2); CH_DECL(3);
    CH_DECL(4); CH_DECL(5); CH_DECL(6); CH_DECL(7);
    if (wid < 16) {
        CH_INIT(0, 0) CH_INIT(1, 1) CH_INIT(2, 2) CH_INIT(3, 3)
        CH_INIT(4, 4) CH_INIT(5, 5) CH_INIT(6, 6) CH_INIT(7, 7)
    }

    // ---- aux roles ----
    int u = 0, dc = 0, wAddr = 0, cA = 0, pIdx = 0;
    float P = 0.f;
    if (tid < 260) {
        u = tid / 65; dc = tid - u * 65;
        wAddr = u * 65 + dc;               // L writeout: band[(j+u)*65+dc]
        cA    = (68 + u) * WS + dc;        // commit: W slot of col j+68+u
        pIdx  = (68 + u) * 65 + dc;        // first prefetch: cols 68..71
    }
    int yr = tid - 256;                    // y-duty r = 4..67 for tid 260..323

    // ---- init ----
    for (int i = tid; i < 1024; i += 544) y_s[i] = g_atb[b * 1024 + i];
    for (int i = 1024 + tid; i < 1100; i += 544) y_s[i] = 0.f;
    for (int i = tid; i < 68 * 65; i += 544) {
        int c = i / 65, d = i - c * 65;
        W[c * WS + d] = band[i];
    }
    for (int i = tid; i < 528; i += 544) PNL[i] = 0.f;
    if (tid < 260) { P = band[pIdx]; pIdx += 260; }
    __syncthreads();

    // ---- main loop: 4 columns per step ----
    int pa = 0;                            // phase-A base: slot(j)*WS
    float xv0 = 0.f, xv1 = 0.f, xv2 = 0.f, xv3 = 0.f;
    for (int j = 0; j < 1024; j += 4) {
        if (wid == 16) {
            // ======== PHASE A: finalize panel cols j..j+3 ========
            float wa0 = W[pa + lane],          wb0 = W[pa + 32 + lane];
            float wa1 = W[pa + WS + lane],     wb1 = W[pa + WS + 32 + lane];
            float wa2 = W[pa + 2 * WS + lane], wb2 = W[pa + 2 * WS + 32 + lane];
            float wa3 = W[pa + 3 * WS + lane], wb3 = W[pa + 3 * WS + 32 + lane];
            float w64_0 = W[pa + 64],          w64_1 = W[pa + WS + 64];
            float w64_2 = W[pa + 2 * WS + 64], w64_3 = W[pa + 3 * WS + 64];

            // t = 0
            float piv = __shfl_sync(0xffffffffu, wa0, 0);
            float rr  = rsqrtf(piv);
            float inv = rr * (1.5f - 0.5f * piv * rr * rr);
            PNL[lane]      = (lane == 0) ? inv : wa0 * inv;
            PNL[32 + lane] = wb0 * inv;
            if (lane == 0) {
                PNL[64] = w64_0 * inv;
                xv0 = y_s[j] * inv;
                x_s[j] = xv0;
            }
            __syncwarp();
            // t = 1  (corrections from t'=0: p=1)
            {
                float lp = PNL[1];
                wa1 -= lp * PNL[1 + lane];
                wb1 -= lp * PNL[33 + lane];
                piv = __shfl_sync(0xffffffffu, wa1, 0);
                rr  = rsqrtf(piv);
                inv = rr * (1.5f - 0.5f * piv * rr * rr);
                PNL[132 + lane]      = (lane == 0) ? inv : wa1 * inv;
                PNL[132 + 32 + lane] = wb1 * inv;
                if (lane == 0) {
                    PNL[132 + 64] = w64_1 * inv;
                    xv1 = (y_s[j + 1] - PNL[1] * xv0) * inv;
                    x_s[j + 1] = xv1;
                }
            }
            __syncwarp();
            // t = 2  (from t'=0: p=2; t'=1: p=1)
            {
                float lpA = PNL[2], lpB = PNL[133];
                wa2 -= lpA * PNL[2 + lane];
                wa2 -= lpB * PNL[133 + lane];
                wb2 -= lpA * PNL[34 + lane];
                wb2 -= lpB * PNL[165 + lane];
                piv = __shfl_sync(0xffffffffu, wa2, 0);
                rr  = rsqrtf(piv);
                inv = rr * (1.5f - 0.5f * piv * rr * rr);
                PNL[264 + lane]      = (lane == 0) ? inv : wa2 * inv;
                PNL[264 + 32 + lane] = wb2 * inv;
                if (lane == 0) {
                    PNL[264 + 64] = w64_2 * inv;
                    xv2 = (y_s[j + 2] - PNL[2] * xv0 - PNL[133] * xv1) * inv;
                    x_s[j + 2] = xv2;
                }
            }
            __syncwarp();
            // t = 3  (from t'=0: p=3; t'=1: p=2; t'=2: p=1)
            {
                float lpA = PNL[3], lpB = PNL[134], lpC = PNL[265];
                wa3 -= lpA * PNL[3 + lane];
                wa3 -= lpB * PNL[134 + lane];
                wa3 -= lpC * PNL[265 + lane];
                wb3 -= lpA * PNL[35 + lane];
                wb3 -= lpB * PNL[166 + lane];
                wb3 -= lpC * PNL[297 + lane];
                piv = __shfl_sync(0xffffffffu, wa3, 0);
                rr  = rsqrtf(piv);
                inv = rr * (1.5f - 0.5f * piv * rr * rr);
                PNL[396 + lane]      = (lane == 0) ? inv : wa3 * inv;
                PNL[396 + 32 + lane] = wb3 * inv;
                if (lane == 0) {
                    PNL[396 + 64] = w64_3 * inv;
                    xv3 = (y_s[j + 3] - PNL[3] * xv0 - PNL[134] * xv1
                           - PNL[265] * xv2) * inv;
                    x_s[j + 3] = xv3;
                }
            }
            pa += 4 * WS; if (pa >= WTOT) pa -= WTOT;
        }
        __syncthreads();

        // ======== PHASE B ========
        if (wid < 16) {
            CH_DO(0) CH_DO(1) CH_DO(2) CH_DO(3)
            CH_DO(4) CH_DO(5) CH_DO(6) CH_DO(7)
        }
        if (tid < 260) {
            band[wAddr] = PNL[u * 132 + dc];          // L writeout (inv at d=0)
            wAddr += 260;
            W[cA] = P;                                 // commit col j+68+u
            cA += 4 * WS; if (cA >= WTOT) cA -= WTOT;
            P = (pIdx < 66560) ? band[pIdx] : 0.f;     // prefetch next
            pIdx += 260;
        } else if (tid < 324) {
            // forward-sub: y[j+r] -= sum_t L_t[r-t] * x_t   (r = 4..67)
            float yv = y_s[j + yr];
            float x0 = x_s[j], x1 = x_s[j + 1], x2 = x_s[j + 2], x3 = x_s[j + 3];
            yv -= PNL[yr]       * x0;
            yv -= PNL[yr + 131] * x1;
            yv -= PNL[yr + 262] * x2;
            yv -= PNL[yr + 393] * x3;
            y_s[j + yr] = yv;
        }
        __syncthreads();
    }
#undef CH_DECL
#undef CH_INIT
#undef CH_DO

    // ---- back substitution: L^T x = y', blocked by 64 rows (reuse W) ----
    float* LB = W;   // stride-65 layout
    for (int blk = 15; blk >= 0; blk--) {
        int j0 = blk * 64;
        for (int idx = tid; idx < 64 * 65; idx += 544)
            LB[idx] = band[j0 * 65 + idx];
        __syncthreads();
        if (tid < 64) {
            int t = tid, jj = j0 + t;
            float s = 0.f;
            for (int r = 64 - t; r <= 64; r++) {
                int jr = jj + r;
                if (jr < 1024) s += LB[t * 65 + r] * x_s[jr];
            }
            x_s[jj] -= s;
        }
        __syncthreads();
        for (int t = 63; t >= 1; t--) {
            float xval = x_s[j0 + t] * LB[t * 65];
            if (tid < t) x_s[j0 + tid] -= LB[tid * 65 + (t - tid)] * xval;
            __syncthreads();
        }
        if (tid < 64) x_s[j0 + tid] *= LB[tid * 65];
        __syncthreads();
    }

    for (int i = tid; i < 1024; i += 544) g_sol[b * 1024 + i] = x_s[i];
}

// ---------------- GroupNorm(1, GR) + affine + SE scale ----------------
__global__ void __launch_bounds__(256) k_gn(const float* __restrict__ gn_g,
                                            const float* __restrict__ gn_b)
{
    int n = blockIdx.x, tid = threadIdx.x;
    __shared__ double s1[256], s2[256];
    double a = 0.0, c = 0.0;
    for (int idx = tid; idx < 4096; idx += 256) {
        double v = g_sol[n * 4096 + idx];
        a += v; c += v * v;
    }
    s1[tid] = a; s2[tid] = c;
    __syncthreads();
    for (int off = 128; off > 0; off >>= 1) {
        if (tid < off) { s1[tid] += s1[tid + off]; s2[tid] += s2[tid + off]; }
        __syncthreads();
    }
    double mu  = s1[0] * (1.0 / 4096.0);
    double var = s2[0] * (1.0 / 4096.0) - mu * mu;
    double invstd = rsqrt(var + 1e-5);
    for (int idx = tid; idx < 4096; idx += 256) {
        int g = idx >> 10;
        float v = (float)((g_sol[n * 4096 + idx] - mu) * invstd);
        v = v * gn_g[g] + gn_b[g];
        v *= g_se[n * 4 + g];
        g_ygn[n * 4096 + idx] = v;
    }
}

// ---------------- final conv: 4->128 3x3 ----------------
__global__ void __launch_bounds__(256) k_convf(
    const float* __restrict__ pw, const float* __restrict__ pb,
    float* __restrict__ out)
{
    int plane = blockIdx.x;          // 0..255
    int n  = plane >> 7;
    int co = plane & 127;
    __shared__ float ys[4 * 1156];
    for (int idx = threadIdx.x; idx < 4 * 1156; idx += 256) {
        int ci = idx / 1156, rr = idx - ci * 1156;
        int r = rr / 34, c = rr - r * 34;
        int gr = r - 1, gc = c - 1;
        ys[idx] = ((unsigned)gr < 32u && (unsigned)gc < 32u)
                  ? g_ygn[(n * 4 + ci) * 1024 + gr * 32 + gc] : 0.f;
    }
    __syncthreads();

    const float* wgt = pw + co * 36;
    float bias = pb[co];
    int row  = threadIdx.x >> 3;
    int col0 = (threadIdx.x & 7) << 2;
    float a0 = bias, a1 = bias, a2 = bias, a3 = bias;
#pragma unroll
    for (int ci = 0; ci < 4; ci++) {
        float w[9];
#pragma unroll
        for (int k = 0; k < 9; k++) w[k] = __ldg(wgt + ci * 9 + k);
        float s[3][6];
#pragma unroll
        for (int dy = 0; dy < 3; dy++)
#pragma unroll
            for (int dx = 0; dx < 6; dx++)
                s[dy][dx] = ys[ci * 1156 + (row + dy) * 34 + col0 + dx];
#pragma unroll
        for (int dy = 0; dy < 3; dy++) {
            float w0 = w[dy * 3], w1 = w[dy * 3 + 1], w2 = w[dy * 3 + 2];
            a0 += w0 * s[dy][0] + w1 * s[dy][1] + w2 * s[dy][2];
            a1 += w0 * s[dy][1] + w1 * s[dy][2] + w2 * s[dy][3];
            a2 += w0 * s[dy][2] + w1 * s[dy][3] + w2 * s[dy][4];
            a3 += w0 * s[dy][3] + w1 * s[dy][4] + w2 * s[dy][5];
        }
    }
    float* o = out + ((n * 128 + co) * 1024) + row * 32 + col0;
    o[0] = a0; o[1] = a1; o[2] = a2; o[3] = a3;
}

// ---------------- launcher (k_solve stays the 4th launch) -------------------
extern "C" void kernel_launch(void* const* d_in, const int* in_sizes, int n_in,
                              void* d_out, int out_size)
{
    const float* x    = (const float*)d_in[0];
    const float* a    = (const float*)d_in[1];
    const float* gw1  = (const float*)d_in[2];
    const float* gb1  = (const float*)d_in[3];
    const float* gw2  = (const float*)d_in[4];
    const float* gb2  = (const float*)d_in[5];
    const float* aw1  = (const float*)d_in[6];
    const float* ab1  = (const float*)d_in[7];
    const float* aw2  = (const float*)d_in[8];
    const float* ab2  = (const float*)d_in[9];
    const float* sw1  = (const float*)d_in[10];
    const float* sb1  = (const float*)d_in[11];
    const float* sw2  = (const float*)d_in[12];
    const float* sb2  = (const float*)d_in[13];
    const float* gn_g = (const float*)d_in[14];
    const float* gn_b = (const float*)d_in[15];
    const float* pw   = (const float*)d_in[16];
    const float* pb   = (const float*)d_in[17];
    float* out = (float*)d_out;

    k_conv1<<<256, 256>>>(x, gw1, gb1, aw1, ab1);
    k_conv2<<<96, 256>>>(gw2, gb2, aw2, ab2);
    k_build<<<32, 256>>>(a);
    k_solve<<<8, 544>>>();
    k_se<<<2, 256>>>(x, sw1, sb1, sw2, sb2);
    k_gn<<<2, 256>>>(gn_g, gn_b);
    k_convf<<<256, 256>>>(pw, pb, out);
}

// round 9
// speedup vs baseline: 1.4928x; 1.1286x over previous
#include <cuda_runtime.h>
#include <math.h>

// ---------------- scratch (static device allocations) ----------------
__device__ float g_band[8 * 1024 * 65];   // banded ATA -> L, [b][col][d], fp32
__device__ float g_atb[8 * 1024];         // rhs
__device__ float g_t[2 * 2 * 64 * 1024];  // conv1 outputs [branch][n][c][px]
__device__ float g_att[2 * 24 * 1024];    // sigmoid(conv2 att)
__device__ float g_grad[2 * 24 * 1024];   // conv2 grad
__device__ float g_se[2 * 4];
__device__ float g_sol[8 * 1024];
__device__ float g_ygn[2 * 4 * 1024];

// ---------------- conv1: 64->64 3x3, lrelu, 2 outputs per block ------------
__global__ void __launch_bounds__(256) k_conv1(
    const float* __restrict__ x,
    const float* __restrict__ gw1, const float* __restrict__ gb1,
    const float* __restrict__ aw1, const float* __restrict__ ab1)
{
    int plane  = blockIdx.x;           // 0..127
    int branch = plane >> 6;           // 0=grad, 1=att
    int n      = (plane >> 5) & 1;
    int co0    = (plane & 31) << 1;    // 0,2,..,62
    const float* wbase = (branch ? aw1 : gw1);
    const float* wgtA  = wbase + co0 * 576;
    const float* wgtB  = wbase + (co0 + 1) * 576;
    float biasA        = (branch ? ab1 : gb1)[co0];
    float biasB        = (branch ? ab1 : gb1)[co0 + 1];

    __shared__ float xs[34 * 34];
    int row  = threadIdx.x >> 3;        // 0..31
    int col0 = (threadIdx.x & 7) << 2;  // 0..28 step 4

    float a0 = biasA, a1 = biasA, a2 = biasA, a3 = biasA;
    float b0 = biasB, b1 = biasB, b2 = biasB, b3 = biasB;
    const float* xbase = x + n * 64 * 1024;

    for (int ci = 0; ci < 64; ci++) {
        __syncthreads();
        const float* xp = xbase + ci * 1024;
        for (int idx = threadIdx.x; idx < 1156; idx += 256) {
            int r = idx / 34, c = idx - r * 34;
            int gr = r - 1, gc = c - 1;
            xs[idx] = ((unsigned)gr < 32u && (unsigned)gc < 32u) ? xp[gr * 32 + gc] : 0.f;
        }
        __syncthreads();
        float wA[9], wB[9];
#pragma unroll
        for (int k = 0; k < 9; k++) { wA[k] = __ldg(wgtA + ci * 9 + k);
                                      wB[k] = __ldg(wgtB + ci * 9 + k); }
        float s[3][6];
#pragma unroll
        for (int dy = 0; dy < 3; dy++)
#pragma unroll
            for (int dx = 0; dx < 6; dx++)
                s[dy][dx] = xs[(row + dy) * 34 + col0 + dx];
#pragma unroll
        for (int dy = 0; dy < 3; dy++) {
            float w0 = wA[dy * 3], w1 = wA[dy * 3 + 1], w2 = wA[dy * 3 + 2];
            a0 += w0 * s[dy][0] + w1 * s[dy][1] + w2 * s[dy][2];
            a1 += w0 * s[dy][1] + w1 * s[dy][2] + w2 * s[dy][3];
            a2 += w0 * s[dy][2] + w1 * s[dy][3] + w2 * s[dy][4];
            a3 += w0 * s[dy][3] + w1 * s[dy][4] + w2 * s[dy][5];
            float v0 = wB[dy * 3], v1 = wB[dy * 3 + 1], v2 = wB[dy * 3 + 2];
            b0 += v0 * s[dy][0] + v1 * s[dy][1] + v2 * s[dy][2];
            b1 += v0 * s[dy][1] + v1 * s[dy][2] + v2 * s[dy][3];
            b2 += v0 * s[dy][2] + v1 * s[dy][3] + v2 * s[dy][4];
            b3 += v0 * s[dy][3] + v1 * s[dy][4] + v2 * s[dy][5];
        }
    }
    float* outA = g_t + (((branch * 2 + n) * 64 + co0) * 1024) + row * 32 + col0;
    float* outB = outA + 1024;
    outA[0] = a0 > 0.f ? a0 : 0.01f * a0;
    outA[1] = a1 > 0.f ? a1 : 0.01f * a1;
    outA[2] = a2 > 0.f ? a2 : 0.01f * a2;
    outA[3] = a3 > 0.f ? a3 : 0.01f * a3;
    outB[0] = b0 > 0.f ? b0 : 0.01f * b0;
    outB[1] = b1 > 0.f ? b1 : 0.01f * b1;
    outB[2] = b2 > 0.f ? b2 : 0.01f * b2;
    outB[3] = b3 > 0.f ? b3 : 0.01f * b3;
}

// ---------------- conv2: 64->24 3x3 (+sigmoid on att branch) ----------------
__global__ void __launch_bounds__(256) k_conv2(
    const float* __restrict__ gw2, const float* __restrict__ gb2,
    const float* __restrict__ aw2, const float* __restrict__ ab2)
{
    int plane  = blockIdx.x;            // 0..95
    int branch = plane / 48;
    int rem    = plane - branch * 48;
    int n      = rem / 24;
    int co     = rem - n * 24;
    const float* wgt = (branch ? aw2 : gw2) + co * 576;
    float bias       = (branch ? ab2 : gb2)[co];

    __shared__ float xs[34 * 34];
    int row  = threadIdx.x >> 3;
    int col0 = (threadIdx.x & 7) << 2;

    float a0 = bias, a1 = bias, a2 = bias, a3 = bias;
    const float* xbase = g_t + (branch * 2 + n) * 64 * 1024;

    for (int ci = 0; ci < 64; ci++) {
        __syncthreads();
        const float* xp = xbase + ci * 1024;
        for (int idx = threadIdx.x; idx < 1156; idx += 256) {
            int r = idx / 34, c = idx - r * 34;
            int gr = r - 1, gc = c - 1;
            xs[idx] = ((unsigned)gr < 32u && (unsigned)gc < 32u) ? xp[gr * 32 + gc] : 0.f;
        }
        __syncthreads();
        float w[9];
#pragma unroll
        for (int k = 0; k < 9; k++) w[k] = __ldg(wgt + ci * 9 + k);
        float s[3][6];
#pragma unroll
        for (int dy = 0; dy < 3; dy++)
#pragma unroll
            for (int dx = 0; dx < 6; dx++)
                s[dy][dx] = xs[(row + dy) * 34 + col0 + dx];
#pragma unroll
        for (int dy = 0; dy < 3; dy++) {
            float w0 = w[dy * 3], w1 = w[dy * 3 + 1], w2 = w[dy * 3 + 2];
            a0 += w0 * s[dy][0] + w1 * s[dy][1] + w2 * s[dy][2];
            a1 += w0 * s[dy][1] + w1 * s[dy][2] + w2 * s[dy][3];
            a2 += w0 * s[dy][2] + w1 * s[dy][3] + w2 * s[dy][4];
            a3 += w0 * s[dy][3] + w1 * s[dy][4] + w2 * s[dy][5];
        }
    }
    float* out = (branch ? g_att : g_grad) + ((n * 24 + co) * 1024) + row * 32 + col0;
    if (branch) {
        out[0] = 1.f / (1.f + expf(-a0));
        out[1] = 1.f / (1.f + expf(-a1));
        out[2] = 1.f / (1.f + expf(-a2));
        out[3] = 1.f / (1.f + expf(-a3));
    } else {
        out[0] = a0; out[1] = a1; out[2] = a2; out[3] = a3;
    }
}

// ---------------- SE branch ----------------
__global__ void __launch_bounds__(256) k_se(
    const float* __restrict__ x,
    const float* __restrict__ sw1, const float* __restrict__ sb1,
    const float* __restrict__ sw2, const float* __restrict__ sb2)
{
    int n = blockIdx.x, tid = threadIdx.x;
    __shared__ float red[256];
    __shared__ float pooled[64];
    __shared__ float s1[32];

    int c = tid >> 2, part = tid & 3;
    const float* xp = x + (n * 64 + c) * 1024 + part * 256;
    float s = 0.f;
    for (int i = 0; i < 256; i++) s += xp[i];
    red[tid] = s;
    __syncthreads();
    if (part == 0)
        pooled[c] = (red[tid] + red[tid + 1] + red[tid + 2] + red[tid + 3]) * (1.f / 1024.f);
    __syncthreads();
    if (tid < 32) {
        float a = sb1[tid];
        for (int j = 0; j < 64; j++) a += sw1[tid * 64 + j] * pooled[j];
        s1[tid] = a > 0.f ? a : 0.01f * a;
    }
    __syncthreads();
    if (tid < 4) {
        float a = sb2[tid];
        for (int j = 0; j < 32; j++) a += sw2[tid * 32 + j] * s1[j];
        g_se[n * 4 + tid] = 1.f / (1.f + expf(-a));
    }
}

// ---------------- build banded ATA + ATB: deterministic gather ----------------
__global__ void __launch_bounds__(256) k_build(const float* __restrict__ a)
{
    int t = blockIdx.x * blockDim.x + threadIdx.x;   // 0..8191
    int b = t >> 10;
    int q = t & 1023;
    int n = b >> 2;
    int g = b & 3;
    const int offs[7] = {0, 1, 2, 31, 32, 33, 64};

    float acc[11];
    const int DVALS[11] = {0, 1, 2, 29, 30, 31, 32, 33, 62, 63, 64};
#pragma unroll
    for (int z = 0; z < 11; z++) acc[z] = 0.f;
    acc[0] = 1e-12f;
    float atb = 0.f;

#pragma unroll
    for (int k = 0; k < 6; k++) {
        int ch = g * 6 + k;
        const float* attp  = g_att  + (n * 24 + ch) * 1024;
        const float* gradp = g_grad + (n * 24 + ch) * 1024;
#pragma unroll
        for (int c2 = 0; c2 < 7; c2++) {
            int i = q - offs[c2];
            if (i >= 0) {
                float attv = attp[i];
                float at2  = attv * attv;
                const float* arow = a + (size_t)(i * 6 + k) * 1024;
                float v2 = arow[q];
                if (v2 != 0.f) {
                    atb += v2 * at2 * gradp[i];
                    float w2 = v2 * at2;
#pragma unroll
                    for (int c1 = c2; c1 < 7; c1++) {
                        int col1 = i + offs[c1];
                        if (col1 <= 1023) {
                            float contrib = arow[col1] * w2;
                            int d = offs[c1] - offs[c2];
#pragma unroll
                            for (int z = 0; z < 11; z++)
                                if (DVALS[z] == d) acc[z] += contrib;
                        }
                    }
                }
            }
        }
    }

    float* bc = g_band + ((size_t)b * 1024 + q) * 65;
#pragma unroll
    for (int d = 0; d < 65; d++) {
        float v = 0.f;
#pragma unroll
        for (int z = 0; z < 11; z++)
            if (DVALS[z] == d) v = acc[z];
        bc[d] = v;
    }
    g_atb[b * 1024 + q] = atb;
}

// ---------------- banded Cholesky, fp32, rank-4 PIPELINED --------------------
// Per step k (panel = cols j..j+3, PNL(k) precomputed in step k-1):
//   NEAR: warps 0..7 apply panel k to cols j+4..7 (1 chunk each);
//         tids 256..259 fwd-sub y r=4..7.        -> barrier
//   CONCURRENT: warp 16 computes Phase A(k+1) on cols j+4..7 (PNL dbl-buf);
//         warps 0..14 apply far chunks (o=8..67, 8 each);
//         warp 15 aux: L writeout, commit cols j+68..71, prefetch, fwd-sub
//         y r=8..67.                             -> barrier
// Phase A latency hidden behind the 120 far chunks.
__global__ void __launch_bounds__(544) k_solve()
{
    const int WS = 68, WTOT = 72 * WS;         // 4896
    int b    = blockIdx.x;
    int tid  = threadIdx.x;
    int wid  = tid >> 5;
    int lane = tid & 31;
    float* band = g_band + (size_t)b * 66560;

    __shared__ float W[4896];
    __shared__ float PNL[1056];        // 2 buffers x 4 cols x 132 (pad 65..131 = 0)
    __shared__ float y_s[1100];
    __shared__ float x_s[1024];

#define CHDO(A, OB, O) { float _w = W[A]; \
        float _l0 = PNL[cb + (O)],       _q0 = PNL[cb + (OB)]; \
        float _l1 = PNL[cb + (O) + 131], _q1 = PNL[cb + (OB) + 131]; \
        float _l2 = PNL[cb + (O) + 262], _q2 = PNL[cb + (OB) + 262]; \
        float _l3 = PNL[cb + (O) + 393], _q3 = PNL[cb + (OB) + 393]; \
        _w -= _l0 * _q0; _w -= _l1 * _q1; _w -= _l2 * _q2; _w -= _l3 * _q3; \
        W[A] = _w; A += 4 * WS; if (A >= WTOT) A -= WTOT; }

    // near chunk (warps 0..7): o = 4..7
    int nA = 0, nOB = 0, nO = 0;
    if (wid < 8) {
        int o = 4 + (wid >> 1), d0 = (wid & 1) << 5;
        nA = o * WS + d0 + lane; nOB = o + d0 + lane; nO = o;
    }
    // far chunks (warps 0..14): o = 8..67
    int fA[8], fOB[8], fO[8];
    if (wid < 15) {
#pragma unroll
        for (int i = 0; i < 8; i++) {
            int idx = wid * 8 + i;
            int o = 8 + (idx >> 1), d0 = (idx & 1) << 5;
            fA[i] = o * WS + d0 + lane; fOB[i] = o + d0 + lane; fO[i] = o;
        }
    }
    // aux (warp 15)
    int aS[9], aA[9], aP[9]; float aV[9];
    if (wid == 15) {
#pragma unroll
        for (int i = 0; i < 9; i++) {
            int idx = lane + 32 * i;
            int u = idx / 65, dc = idx - u * 65;
            aS[i] = u * 132 + dc;
            aA[i] = (68 + u) * WS + dc;
            aP[i] = 4680 + idx;
            aV[i] = 0.f;
        }
    }
    int jw = 0;

    // ---- init ----
    for (int i = tid; i < 1024; i += 544) y_s[i] = g_atb[b * 1024 + i];
    for (int i = 1024 + tid; i < 1100; i += 544) y_s[i] = 0.f;
    for (int i = tid; i < 4420; i += 544) {
        int c = i / 65, d = i - c * 65;
        W[c * WS + d] = band[i];
    }
    for (int i = tid; i < 1056; i += 544) PNL[i] = 0.f;
    if (wid == 15) {
#pragma unroll
        for (int i = 0; i < 9; i++) {
            int idx = lane + 32 * i;
            if (idx < 260) aV[i] = band[4420 + idx];
        }
    }
    __syncthreads();

    int pa = 0;
    auto phaseA = [&](int j4, int nb) {
        float wa0 = W[pa + lane],          wb0 = W[pa + 32 + lane];
        float wa1 = W[pa + WS + lane],     wb1 = W[pa + WS + 32 + lane];
        float wa2 = W[pa + 2 * WS + lane], wb2 = W[pa + 2 * WS + 32 + lane];
        float wa3 = W[pa + 3 * WS + lane], wb3 = W[pa + 3 * WS + 32 + lane];
        float w64_0 = W[pa + 64],          w64_1 = W[pa + WS + 64];
        float w64_2 = W[pa + 2 * WS + 64], w64_3 = W[pa + 3 * WS + 64];
        float xv0 = 0.f, xv1 = 0.f, xv2 = 0.f;
        // t = 0
        float piv = __shfl_sync(0xffffffffu, wa0, 0);
        float rr  = rsqrtf(piv);
        float inv = rr * (1.5f - 0.5f * piv * rr * rr);
        PNL[nb + lane]      = (lane == 0) ? inv : wa0 * inv;
        PNL[nb + 32 + lane] = wb0 * inv;
        if (lane == 0) {
            PNL[nb + 64] = w64_0 * inv;
            xv0 = y_s[j4] * inv;
            x_s[j4] = xv0;
        }
        __syncwarp();
        // t = 1
        {
            float lp = PNL[nb + 1];
            wa1 -= lp * PNL[nb + 1 + lane];
            wb1 -= lp * PNL[nb + 33 + lane];
            piv = __shfl_sync(0xffffffffu, wa1, 0);
            rr  = rsqrtf(piv);
            inv = rr * (1.5f - 0.5f * piv * rr * rr);
            PNL[nb + 132 + lane]      = (lane == 0) ? inv : wa1 * inv;
            PNL[nb + 164 + lane] = wb1 * inv;
            if (lane == 0) {
                PNL[nb + 196] = w64_1 * inv;
                xv1 = (y_s[j4 + 1] - PNL[nb + 1] * xv0) * inv;
                x_s[j4 + 1] = xv1;
            }
        }
        __syncwarp();
        // t = 2
        {
            float lpA = PNL[nb + 2], lpB = PNL[nb + 133];
            wa2 -= lpA * PNL[nb + 2 + lane];
            wa2 -= lpB * PNL[nb + 133 + lane];
            wb2 -= lpA * PNL[nb + 34 + lane];
            wb2 -= lpB * PNL[nb + 165 + lane];
            piv = __shfl_sync(0xffffffffu, wa2, 0);
            rr  = rsqrtf(piv);
            inv = rr * (1.5f - 0.5f * piv * rr * rr);
            PNL[nb + 264 + lane]      = (lane == 0) ? inv : wa2 * inv;
            PNL[nb + 296 + lane] = wb2 * inv;
            if (lane == 0) {
                PNL[nb + 328] = w64_2 * inv;
                xv2 = (y_s[j4 + 2] - PNL[nb + 2] * xv0 - PNL[nb + 133] * xv1) * inv;
                x_s[j4 + 2] = xv2;
            }
        }
        __syncwarp();
        // t = 3
        {
            float lpA = PNL[nb + 3], lpB = PNL[nb + 134], lpC = PNL[nb + 265];
            wa3 -= lpA * PNL[nb + 3 + lane];
            wa3 -= lpB * PNL[nb + 134 + lane];
            wa3 -= lpC * PNL[nb + 265 + lane];
            wb3 -= lpA * PNL[nb + 35 + lane];
            wb3 -= lpB * PNL[nb + 166 + lane];
            wb3 -= lpC * PNL[nb + 297 + lane];
            piv = __shfl_sync(0xffffffffu, wa3, 0);
            rr  = rsqrtf(piv);
            inv = rr * (1.5f - 0.5f * piv * rr * rr);
            PNL[nb + 396 + lane]      = (lane == 0) ? inv : wa3 * inv;
            PNL[nb + 428 + lane] = wb3 * inv;
            if (lane == 0) {
                PNL[nb + 460] = w64_3 * inv;
                float xv3 = (y_s[j4 + 3] - PNL[nb + 3] * xv0
                             - PNL[nb + 134] * xv1 - PNL[nb + 265] * xv2) * inv;
                x_s[j4 + 3] = xv3;
            }
        }
        pa += 4 * WS; if (pa >= WTOT) pa -= WTOT;
    };

    // ---- prologue: Phase A(0) on cols 0..3 (buffer 0) ----
    if (wid == 16) phaseA(0, 0);
    __syncthreads();

    // ---- main loop: one pipelined step per panel ----
    for (int k = 0; k < 256; k++) {
        int j  = k << 2;
        int cb = (k & 1) * 528;

        // ===== NEAR =====
        if (wid < 8) {
            CHDO(nA, nOB, nO)
        }
        if (tid >= 256 && tid < 260) {
            int r = tid - 252;   // 4..7
            float yv = y_s[j + r];
            yv -= PNL[cb + r]       * x_s[j];
            yv -= PNL[cb + r + 131] * x_s[j + 1];
            yv -= PNL[cb + r + 262] * x_s[j + 2];
            yv -= PNL[cb + r + 393] * x_s[j + 3];
            y_s[j + r] = yv;
        }
        __syncthreads();

        // ===== CONCURRENT =====
        if (wid == 16) {
            if (k < 255) phaseA(j + 4, 528 - cb);
        } else if (wid < 15) {
            CHDO(fA[0], fOB[0], fO[0])
            CHDO(fA[1], fOB[1], fO[1])
            CHDO(fA[2], fOB[2], fO[2])
            CHDO(fA[3], fOB[3], fO[3])
            CHDO(fA[4], fOB[4], fO[4])
            CHDO(fA[5], fOB[5], fO[5])
            CHDO(fA[6], fOB[6], fO[6])
            CHDO(fA[7], fOB[7], fO[7])
        } else {
            float x0 = x_s[j], x1 = x_s[j + 1], x2 = x_s[j + 2], x3 = x_s[j + 3];
#pragma unroll
            for (int i = 0; i < 9; i++) {
                if (i < 8 || lane < 4) {
                    int idx = lane + 32 * i;
                    band[jw + idx] = PNL[cb + aS[i]];        // L writeout
                    W[aA[i]] = aV[i];                        // commit col j+68+u
                    aA[i] += 4 * WS; if (aA[i] >= WTOT) aA[i] -= WTOT;
                    aV[i] = (aP[i] < 66560) ? band[aP[i]] : 0.f;  // prefetch
                    aP[i] += 260;
                }
            }
            jw += 260;
            int r = 8 + lane;
            float yv = y_s[j + r];
            yv -= PNL[cb + r]       * x0;
            yv -= PNL[cb + r + 131] * x1;
            yv -= PNL[cb + r + 262] * x2;
            yv -= PNL[cb + r + 393] * x3;
            y_s[j + r] = yv;
            r = 40 + lane;
            if (r <= 67) {
                float yv2 = y_s[j + r];
                yv2 -= PNL[cb + r]       * x0;
                yv2 -= PNL[cb + r + 131] * x1;
                yv2 -= PNL[cb + r + 262] * x2;
                yv2 -= PNL[cb + r + 393] * x3;
                y_s[j + r] = yv2;
            }
        }
        __syncthreads();
    }
#undef CHDO

    // ---- back substitution: L^T x = y', blocked by 64 rows (reuse W) ----
    float* LB = W;   // stride-65 layout
    for (int blk = 15; blk >= 0; blk--) {
        int j0 = blk * 64;
        for (int idx = tid; idx < 64 * 65; idx += 544)
            LB[idx] = band[j0 * 65 + idx];
        __syncthreads();
        if (tid < 64) {
            int t = tid, jj = j0 + t;
            float s = 0.f;
            for (int r = 64 - t; r <= 64; r++) {
                int jr = jj + r;
                if (jr < 1024) s += LB[t * 65 + r] * x_s[jr];
            }
            x_s[jj] -= s;
        }
        __syncthreads();
        for (int t = 63; t >= 1; t--) {
            float xval = x_s[j0 + t] * LB[t * 65];
            if (tid < t) x_s[j0 + tid] -= LB[tid * 65 + (t - tid)] * xval;
            __syncthreads();
        }
        if (tid < 64) x_s[j0 + tid] *= LB[tid * 65];
        __syncthreads();
    }

    for (int i = tid; i < 1024; i += 544) g_sol[b * 1024 + i] = x_s[i];
}

// ---------------- GroupNorm(1, GR) + affine + SE scale ----------------
__global__ void __launch_bounds__(256) k_gn(const float* __restrict__ gn_g,
                                            const float* __restrict__ gn_b)
{
    int n = blockIdx.x, tid = threadIdx.x;
    __shared__ double s1[256], s2[256];
    double a = 0.0, c = 0.0;
    for (int idx = tid; idx < 4096; idx += 256) {
        double v = g_sol[n * 4096 + idx];
        a += v; c += v * v;
    }
    s1[tid] = a; s2[tid] = c;
    __syncthreads();
    for (int off = 128; off > 0; off >>= 1) {
        if (tid < off) { s1[tid] += s1[tid + off]; s2[tid] += s2[tid + off]; }
        __syncthreads();
    }
    double mu  = s1[0] * (1.0 / 4096.0);
    double var = s2[0] * (1.0 / 4096.0) - mu * mu;
    double invstd = rsqrt(var + 1e-5);
    for (int idx = tid; idx < 4096; idx += 256) {
        int g = idx >> 10;
        float v = (float)((g_sol[n * 4096 + idx] - mu) * invstd);
        v = v * gn_g[g] + gn_b[g];
        v *= g_se[n * 4 + g];
        g_ygn[n * 4096 + idx] = v;
    }
}

// ---------------- final conv: 4->128 3x3 ----------------
__global__ void __launch_bounds__(256) k_convf(
    const float* __restrict__ pw, const float* __restrict__ pb,
    float* __restrict__ out)
{
    int plane = blockIdx.x;          // 0..255
    int n  = plane >> 7;
    int co = plane & 127;
    __shared__ float ys[4 * 1156];
    for (int idx = threadIdx.x; idx < 4 * 1156; idx += 256) {
        int ci = idx / 1156, rr = idx - ci * 1156;
        int r = rr / 34, c = rr - r * 34;
        int gr = r - 1, gc = c - 1;
        ys[idx] = ((unsigned)gr < 32u && (unsigned)gc < 32u)
                  ? g_ygn[(n * 4 + ci) * 1024 + gr * 32 + gc] : 0.f;
    }
    __syncthreads();

    const float* wgt = pw + co * 36;
    float bias = pb[co];
    int row  = threadIdx.x >> 3;
    int col0 = (threadIdx.x & 7) << 2;
    float a0 = bias, a1 = bias, a2 = bias, a3 = bias;
#pragma unroll
    for (int ci = 0; ci < 4; ci++) {
        float w[9];
#pragma unroll
        for (int k = 0; k < 9; k++) w[k] = __ldg(wgt + ci * 9 + k);
        float s[3][6];
#pragma unroll
        for (int dy = 0; dy < 3; dy++)
#pragma unroll
            for (int dx = 0; dx < 6; dx++)
                s[dy][dx] = ys[ci * 1156 + (row + dy) * 34 + col0 + dx];
#pragma unroll
        for (int dy = 0; dy < 3; dy++) {
            float w0 = w[dy * 3], w1 = w[dy * 3 + 1], w2 = w[dy * 3 + 2];
            a0 += w0 * s[dy][0] + w1 * s[dy][1] + w2 * s[dy][2];
            a1 += w0 * s[dy][1] + w1 * s[dy][2] + w2 * s[dy][3];
            a2 += w0 * s[dy][2] + w1 * s[dy][3] + w2 * s[dy][4];
            a3 += w0 * s[dy][3] + w1 * s[dy][4] + w2 * s[dy][5];
        }
    }
    float* o = out + ((n * 128 + co) * 1024) + row * 32 + col0;
    o[0] = a0; o[1] = a1; o[2] = a2; o[3] = a3;
}

// ---------------- launcher (k_solve stays the 4th launch) -------------------
extern "C" void kernel_launch(void* const* d_in, const int* in_sizes, int n_in,
                              void* d_out, int out_size)
{
    const float* x    = (const float*)d_in[0];
    const float* a    = (const float*)d_in[1];
    const float* gw1  = (const float*)d_in[2];
    const float* gb1  = (const float*)d_in[3];
    const float* gw2  = (const float*)d_in[4];
    const float* gb2  = (const float*)d_in[5];
    const float* aw1  = (const float*)d_in[6];
    const float* ab1  = (const float*)d_in[7];
    const float* aw2  = (const float*)d_in[8];
    const float* ab2  = (const float*)d_in[9];
    const float* sw1  = (const float*)d_in[10];
    const float* sb1  = (const float*)d_in[11];
    const float* sw2  = (const float*)d_in[12];
    const float* sb2  = (const float*)d_in[13];
    const float* gn_g = (const float*)d_in[14];
    const float* gn_b = (const float*)d_in[15];
    const float* pw   = (const float*)d_in[16];
    const float* pb   = (const float*)d_in[17];
    float* out = (float*)d_out;

    k_conv1<<<128, 256>>>(x, gw1, gb1, aw1, ab1);
    k_conv2<<<96, 256>>>(gw2, gb2, aw2, ab2);
    k_build<<<32, 256>>>(a);
    k_solve<<<8, 544>>>();
    k_se<<<2, 256>>>(x, sw1, sb1, sw2, sb2);
    k_gn<<<2, 256>>>(gn_g, gn_b);
    k_convf<<<256, 256>>>(pw, pb, out);
}